// round 7
// baseline (speedup 1.0000x reference)
#include <cuda_runtime.h>
#include <cuda_fp16.h>
#include <cstdint>

// ---------------------------------------------------------------------------
// out[M,N] = x[M,K] @ (codes[N,K] * scale)^T + bias
// M=8192, N=4096, K=4096.  Baseline sm_100 ISA: HMMA m16n8k16 + ldmatrix +
// cp.async.
// R6 change: warp tile 64x32 -> 64x64 (8 warps, 4m x 2n, 256 threads) to cut
// SMEM crossbar read duplication (192KB -> 128KB reads per k-iter), which the
// resource model says is the binding pipe, not HMMA issue.
// ---------------------------------------------------------------------------
#define M_DIM 8192
#define N_DIM 4096
#define K_DIM 4096

#define BM 256
#define BN 128
#define BK 64
#define STAGES 4
#define KITERS (K_DIM / BK)          // 64

#define A_TILE_BYTES (BM * BK * 2)   // 32 KB
#define B_TILE_BYTES (BN * BK * 2)   // 16 KB
#define STAGE_BYTES  (A_TILE_BYTES + B_TILE_BYTES)   // 48 KB
#define SMEM_BYTES   (STAGES * STAGE_BYTES)          // 192 KB

// Scratch fp16 copies (device globals: allocation-free per harness rules)
__device__ __align__(1024) __half g_Xh[(size_t)M_DIM * K_DIM];   // 64 MB
__device__ __align__(1024) __half g_Wh[(size_t)N_DIM * K_DIM];   // 32 MB

// ---------------------------------------------------------------------------
// PTX helpers
// ---------------------------------------------------------------------------
__device__ __forceinline__ uint32_t smem_u32(const void* p) {
    uint32_t a;
    asm("{ .reg .u64 t; cvta.to.shared.u64 t, %1; cvt.u32.u64 %0, t; }"
        : "=r"(a) : "l"(p));
    return a;
}

__device__ __forceinline__ void cp16(uint32_t dst, const void* src) {
    asm volatile("cp.async.cg.shared.global [%0], [%1], 16;"
                 :: "r"(dst), "l"(src) : "memory");
}
__device__ __forceinline__ void cp_commit() {
    asm volatile("cp.async.commit_group;" ::: "memory");
}
template <int N>
__device__ __forceinline__ void cp_wait() {
    asm volatile("cp.async.wait_group %0;" :: "n"(N) : "memory");
}

__device__ __forceinline__ void ldmatrix_x4(uint32_t* r, uint32_t addr) {
    asm volatile("ldmatrix.sync.aligned.m8n8.x4.shared.b16 {%0,%1,%2,%3}, [%4];"
                 : "=r"(r[0]), "=r"(r[1]), "=r"(r[2]), "=r"(r[3]) : "r"(addr));
}

__device__ __forceinline__ void mma16816(float* c, const uint32_t* a,
                                         const uint32_t* b) {
    asm volatile(
        "mma.sync.aligned.m16n8k16.row.col.f32.f16.f16.f32 "
        "{%0,%1,%2,%3}, {%4,%5,%6,%7}, {%8,%9}, {%0,%1,%2,%3};"
        : "+f"(c[0]), "+f"(c[1]), "+f"(c[2]), "+f"(c[3])
        : "r"(a[0]), "r"(a[1]), "r"(a[2]), "r"(a[3]), "r"(b[0]), "r"(b[1]));
}

// ---------------------------------------------------------------------------
// Conversion pre-passes: fp32 x -> fp16, int32 codes -> fp16 (exact)
// ---------------------------------------------------------------------------
struct __align__(16) H8 { __half2 a, b, c, d; };
struct __align__(8)  H4 { __half2 a, b; };

__global__ void fp4lin_cvt_x(const float4* __restrict__ x, H8* __restrict__ o, int n8) {
    int i = blockIdx.x * blockDim.x + threadIdx.x;
    if (i >= n8) return;
    float4 v0 = x[2 * i], v1 = x[2 * i + 1];
    H8 h;
    h.a = __floats2half2_rn(v0.x, v0.y);
    h.b = __floats2half2_rn(v0.z, v0.w);
    h.c = __floats2half2_rn(v1.x, v1.y);
    h.d = __floats2half2_rn(v1.z, v1.w);
    o[i] = h;
}

__global__ void fp4lin_cvt_w(const int4* __restrict__ w, H4* __restrict__ o, int n4) {
    int i = blockIdx.x * blockDim.x + threadIdx.x;
    if (i >= n4) return;
    int4 v = w[i];
    H4 h;
    h.a = __halves2half2(__int2half_rn(v.x), __int2half_rn(v.y));
    h.b = __halves2half2(__int2half_rn(v.z), __int2half_rn(v.w));
    o[i] = h;
}

// ---------------------------------------------------------------------------
// GEMM: 256x128x64 CTA tile, 8 warps (4m x 2n, 64x64 warp tile),
// 4-stage cp.async pipeline, XOR-swizzled SMEM, HMMA m16n8k16.
//
// SMEM tile layout (A: 256 rows, B: 128 rows; 8 granules of 16B per row),
// granule stored at (g ^ (row & 7)) -> conflict-free cp.async stores AND
// conflict-free ldmatrix reads.
// ---------------------------------------------------------------------------
__global__ void __launch_bounds__(256, 1)
fp4lin_gemm(const __half* __restrict__ Ag, const __half* __restrict__ Bg,
            const float* __restrict__ scale_p, const float* __restrict__ bias,
            float* __restrict__ out) {
    extern __shared__ __align__(1024) uint8_t smem[];
    const uint32_t sbase = smem_u32(smem);
    const int tid  = threadIdx.x;
    const int wid  = tid >> 5;
    const int lane = tid & 31;
    const int wm   = wid >> 1;          // 0..3  (m warp)
    const int wn   = wid & 1;           // 0..1  (n warp)
    const int m0   = blockIdx.y * BM;
    const int n0   = blockIdx.x * BN;

    // --- cp.async per-thread mapping (fixed across stages) ---
    // A: 2048 granules -> 8 per thread (rows trow + i*32, i=0..7)
    // B: 1024 granules -> 4 per thread (rows trow + i*32, i=0..3)
    const int trow = tid >> 3;                 // 0..31
    const int tgc  = tid & 7;                  // granule col 0..7
    const uint32_t swg   = (uint32_t)(tgc ^ (trow & 7));
    const uint32_t s_off = (uint32_t)trow * 128u + swg * 16u;
    const __half* gA0 = Ag + (size_t)(m0 + trow) * K_DIM + tgc * 8;
    const __half* gB0 = Bg + (size_t)(n0 + trow) * K_DIM + tgc * 8;

    // --- ldmatrix per-lane components ---
    const int rowin  = (lane & 7) | (((lane >> 3) & 1) << 3);  // 0..15
    const int colsel = lane >> 4;                              // 0..1
    const int lane7  = lane & 7;
    uint32_t aRowOff[4];
#pragma unroll
    for (int t = 0; t < 4; t++)
        aRowOff[t] = (uint32_t)(wm * 64 + t * 16 + rowin) * 128u;
    uint32_t bRowOff[4];
#pragma unroll
    for (int t = 0; t < 4; t++)
        bRowOff[t] = (uint32_t)(wn * 64 + t * 16 + rowin) * 128u;

    float acc[4][8][4];
#pragma unroll
    for (int mt = 0; mt < 4; mt++)
#pragma unroll
        for (int nt = 0; nt < 8; nt++)
#pragma unroll
            for (int e = 0; e < 4; e++) acc[mt][nt][e] = 0.f;

#define LOAD_STAGE(s, kblk)                                                     \
    do {                                                                        \
        const uint32_t sA = sbase + (uint32_t)(s) * STAGE_BYTES;                \
        const uint32_t sB = sA + A_TILE_BYTES;                                  \
        _Pragma("unroll")                                                       \
        for (int i = 0; i < 8; i++)                                             \
            cp16(sA + s_off + (uint32_t)i * 32u * 128u,                         \
                 gA0 + (size_t)i * 32 * K_DIM + (kblk));                        \
        _Pragma("unroll")                                                       \
        for (int i = 0; i < 4; i++)                                             \
            cp16(sB + s_off + (uint32_t)i * 32u * 128u,                         \
                 gB0 + (size_t)i * 32 * K_DIM + (kblk));                        \
        cp_commit();                                                            \
    } while (0)

    // Prologue: fill STAGES-1 stages
#pragma unroll
    for (int s = 0; s < STAGES - 1; s++) LOAD_STAGE(s, s * BK);

    int sr = 0, sw = STAGES - 1;
    for (int k = 0; k < KITERS; k++) {
        cp_wait<STAGES - 2>();
        __syncthreads();

        // issue the next stage's loads (keeps pipeline full)
        if (k + STAGES - 1 < KITERS) LOAD_STAGE(sw, (k + STAGES - 1) * BK);
        else cp_commit();   // keep wait_group counting consistent

        const uint32_t sA = sbase + (uint32_t)sr * STAGE_BYTES;
        const uint32_t sB = sA + A_TILE_BYTES;

#pragma unroll
        for (int ks = 0; ks < BK / 16; ks++) {
            const uint32_t swz = (uint32_t)(((ks * 2 + colsel) ^ lane7)) * 16u;
            uint32_t a[4][4];
#pragma unroll
            for (int mt = 0; mt < 4; mt++)
                ldmatrix_x4(a[mt], sA + aRowOff[mt] + swz);
            uint32_t b[8][2];
#pragma unroll
            for (int j = 0; j < 4; j++) {
                uint32_t r[4];
                ldmatrix_x4(r, sB + bRowOff[j] + swz);
                b[2 * j][0]     = r[0];
                b[2 * j + 1][0] = r[1];
                b[2 * j][1]     = r[2];
                b[2 * j + 1][1] = r[3];
            }
#pragma unroll
            for (int mt = 0; mt < 4; mt++)
#pragma unroll
                for (int nt = 0; nt < 8; nt++)
                    mma16816(acc[mt][nt], a[mt], b[nt]);
        }

        sr = (sr + 1) % STAGES;
        sw = (sw + 1) % STAGES;
    }

    // ------------------------------ epilogue -------------------------------
    const float sc = *scale_p;
    const int mbase = m0 + wm * 64 + (lane >> 2);
    const int nbase = n0 + wn * 64 + (lane & 3) * 2;
#pragma unroll
    for (int nt = 0; nt < 8; nt++) {
        const int n = nbase + nt * 8;
        const float2 bb = *reinterpret_cast<const float2*>(bias + n);
#pragma unroll
        for (int mt = 0; mt < 4; mt++) {
            const int m = mbase + mt * 16;
            float2 o0, o1;
            o0.x = acc[mt][nt][0] * sc + bb.x;
            o0.y = acc[mt][nt][1] * sc + bb.y;
            o1.x = acc[mt][nt][2] * sc + bb.x;
            o1.y = acc[mt][nt][3] * sc + bb.y;
            *reinterpret_cast<float2*>(out + (size_t)m * N_DIM + n) = o0;
            *reinterpret_cast<float2*>(out + (size_t)(m + 8) * N_DIM + n) = o1;
        }
    }
#undef LOAD_STAGE
}

// ---------------------------------------------------------------------------
// Host launch
// ---------------------------------------------------------------------------
extern "C" void kernel_launch(void* const* d_in, const int* in_sizes, int n_in,
                              void* d_out, int out_size) {
    (void)in_sizes; (void)n_in; (void)out_size;
    const float* x     = (const float*)d_in[0];
    const int*   w     = (const int*)d_in[1];
    const float* scale = (const float*)d_in[2];
    const float* bias  = (const float*)d_in[3];
    float*       out   = (float*)d_out;

    void *xh = nullptr, *wh = nullptr;
    cudaGetSymbolAddress(&xh, g_Xh);
    cudaGetSymbolAddress(&wh, g_Wh);

    {
        const int n8 = M_DIM * K_DIM / 8;
        fp4lin_cvt_x<<<n8 / 256, 256>>>((const float4*)x, (H8*)xh, n8);
        const int n4 = N_DIM * K_DIM / 4;
        fp4lin_cvt_w<<<n4 / 256, 256>>>((const int4*)w, (H4*)wh, n4);
    }

    static bool attr_set = false;
    if (!attr_set) {
        cudaFuncSetAttribute(fp4lin_gemm,
                             cudaFuncAttributeMaxDynamicSharedMemorySize,
                             SMEM_BYTES);
        attr_set = true;
    }
    dim3 grid(N_DIM / BN, M_DIM / BM);   // 32 x 32; x = n fastest
    fp4lin_gemm<<<grid, 256, SMEM_BYTES>>>((const __half*)xh, (const __half*)wh,
                                           scale, bias, out);
}

// round 8
// speedup vs baseline: 1.1109x; 1.1109x over previous
#include <cuda_runtime.h>
#include <cuda_fp16.h>
#include <cstdint>

// ---------------------------------------------------------------------------
// out[M,N] = x[M,K] @ (codes[N,K] * scale)^T + bias
// M=8192, N=4096, K=4096.  Baseline sm_100 ISA: HMMA m16n8k16 + ldmatrix +
// cp.async.
// R7 change: evidence says issue/latency-bound, not smem-bound. Go back to
// 128x128 CTA tile (8 warps, 2m x 4n, 64x32 warp tile) but with 3 stages
// (96 KB SMEM) and __launch_bounds__(256, 2) -> 2 CTAs/SM. 4 warps/SMSP from
// INDEPENDENT CTAs: one CTA's syncthreads/pipeline bubbles are hidden by the
// other CTA's HMMA work.
// ---------------------------------------------------------------------------
#define M_DIM 8192
#define N_DIM 4096
#define K_DIM 4096

#define BM 128
#define BN 128
#define BK 64
#define STAGES 3
#define KITERS (K_DIM / BK)          // 64

#define A_TILE_BYTES (BM * BK * 2)   // 16 KB
#define B_TILE_BYTES (BN * BK * 2)   // 16 KB
#define STAGE_BYTES  (A_TILE_BYTES + B_TILE_BYTES)   // 32 KB
#define SMEM_BYTES   (STAGES * STAGE_BYTES)          // 96 KB -> 2 CTAs/SM

// Scratch fp16 copies (device globals: allocation-free per harness rules)
__device__ __align__(1024) __half g_Xh[(size_t)M_DIM * K_DIM];   // 64 MB
__device__ __align__(1024) __half g_Wh[(size_t)N_DIM * K_DIM];   // 32 MB

// ---------------------------------------------------------------------------
// PTX helpers
// ---------------------------------------------------------------------------
__device__ __forceinline__ uint32_t smem_u32(const void* p) {
    uint32_t a;
    asm("{ .reg .u64 t; cvta.to.shared.u64 t, %1; cvt.u32.u64 %0, t; }"
        : "=r"(a) : "l"(p));
    return a;
}

__device__ __forceinline__ void cp16(uint32_t dst, const void* src) {
    asm volatile("cp.async.cg.shared.global [%0], [%1], 16;"
                 :: "r"(dst), "l"(src) : "memory");
}
__device__ __forceinline__ void cp_commit() {
    asm volatile("cp.async.commit_group;" ::: "memory");
}
template <int N>
__device__ __forceinline__ void cp_wait() {
    asm volatile("cp.async.wait_group %0;" :: "n"(N) : "memory");
}

__device__ __forceinline__ void ldmatrix_x4(uint32_t* r, uint32_t addr) {
    asm volatile("ldmatrix.sync.aligned.m8n8.x4.shared.b16 {%0,%1,%2,%3}, [%4];"
                 : "=r"(r[0]), "=r"(r[1]), "=r"(r[2]), "=r"(r[3]) : "r"(addr));
}

__device__ __forceinline__ void mma16816(float* c, const uint32_t* a,
                                         const uint32_t* b) {
    asm volatile(
        "mma.sync.aligned.m16n8k16.row.col.f32.f16.f16.f32 "
        "{%0,%1,%2,%3}, {%4,%5,%6,%7}, {%8,%9}, {%0,%1,%2,%3};"
        : "+f"(c[0]), "+f"(c[1]), "+f"(c[2]), "+f"(c[3])
        : "r"(a[0]), "r"(a[1]), "r"(a[2]), "r"(a[3]), "r"(b[0]), "r"(b[1]));
}

// ---------------------------------------------------------------------------
// Conversion pre-passes: fp32 x -> fp16, int32 codes -> fp16 (exact)
// ---------------------------------------------------------------------------
struct __align__(16) H8 { __half2 a, b, c, d; };
struct __align__(8)  H4 { __half2 a, b; };

__global__ void fp4lin_cvt_x(const float4* __restrict__ x, H8* __restrict__ o, int n8) {
    int i = blockIdx.x * blockDim.x + threadIdx.x;
    if (i >= n8) return;
    float4 v0 = x[2 * i], v1 = x[2 * i + 1];
    H8 h;
    h.a = __floats2half2_rn(v0.x, v0.y);
    h.b = __floats2half2_rn(v0.z, v0.w);
    h.c = __floats2half2_rn(v1.x, v1.y);
    h.d = __floats2half2_rn(v1.z, v1.w);
    o[i] = h;
}

__global__ void fp4lin_cvt_w(const int4* __restrict__ w, H4* __restrict__ o, int n4) {
    int i = blockIdx.x * blockDim.x + threadIdx.x;
    if (i >= n4) return;
    int4 v = w[i];
    H4 h;
    h.a = __halves2half2(__int2half_rn(v.x), __int2half_rn(v.y));
    h.b = __halves2half2(__int2half_rn(v.z), __int2half_rn(v.w));
    o[i] = h;
}

// ---------------------------------------------------------------------------
// GEMM: 128x128x64 CTA tile, 8 warps (2m x 4n, 64x32 warp tile),
// 3-stage cp.async pipeline, XOR-swizzled SMEM, HMMA m16n8k16, 2 CTAs/SM.
//
// SMEM tile layout (both A and B: 128 rows; 8 granules of 16B per row),
// granule stored at (g ^ (row & 7)) -> conflict-free cp.async stores AND
// conflict-free ldmatrix reads.
// ---------------------------------------------------------------------------
__global__ void __launch_bounds__(256, 2)
fp4lin_gemm(const __half* __restrict__ Ag, const __half* __restrict__ Bg,
            const float* __restrict__ scale_p, const float* __restrict__ bias,
            float* __restrict__ out) {
    extern __shared__ __align__(1024) uint8_t smem[];
    const uint32_t sbase = smem_u32(smem);
    const int tid  = threadIdx.x;
    const int wid  = tid >> 5;
    const int lane = tid & 31;
    const int wm   = wid >> 2;          // 0..1  (m warp)
    const int wn   = wid & 3;           // 0..3  (n warp)
    const int m0   = blockIdx.y * BM;
    const int n0   = blockIdx.x * BN;

    // --- cp.async per-thread mapping (fixed across stages) ---
    // A: 1024 granules -> 4 per thread (rows trow + i*32), same for B.
    const int trow = tid >> 3;                 // 0..31
    const int tgc  = tid & 7;                  // granule col 0..7
    const uint32_t swg   = (uint32_t)(tgc ^ (trow & 7));
    const uint32_t s_off = (uint32_t)trow * 128u + swg * 16u;
    const __half* gA0 = Ag + (size_t)(m0 + trow) * K_DIM + tgc * 8;
    const __half* gB0 = Bg + (size_t)(n0 + trow) * K_DIM + tgc * 8;

    // --- ldmatrix per-lane components ---
    const int rowin  = (lane & 7) | (((lane >> 3) & 1) << 3);  // 0..15
    const int colsel = lane >> 4;                              // 0..1
    const int lane7  = lane & 7;
    uint32_t aRowOff[4];
#pragma unroll
    for (int t = 0; t < 4; t++)
        aRowOff[t] = (uint32_t)(wm * 64 + t * 16 + rowin) * 128u;
    const uint32_t bRow0 = (uint32_t)(wn * 32 + rowin) * 128u;
    const uint32_t bRow1 = (uint32_t)(wn * 32 + 16 + rowin) * 128u;

    float acc[4][4][4];
#pragma unroll
    for (int mt = 0; mt < 4; mt++)
#pragma unroll
        for (int nt = 0; nt < 4; nt++)
#pragma unroll
            for (int e = 0; e < 4; e++) acc[mt][nt][e] = 0.f;

#define LOAD_STAGE(s, kblk)                                                     \
    do {                                                                        \
        const uint32_t sA = sbase + (uint32_t)(s) * STAGE_BYTES;                \
        const uint32_t sB = sA + A_TILE_BYTES;                                  \
        _Pragma("unroll")                                                       \
        for (int i = 0; i < 4; i++) {                                           \
            cp16(sA + s_off + (uint32_t)i * 32u * 128u,                         \
                 gA0 + (size_t)i * 32 * K_DIM + (kblk));                        \
            cp16(sB + s_off + (uint32_t)i * 32u * 128u,                         \
                 gB0 + (size_t)i * 32 * K_DIM + (kblk));                        \
        }                                                                       \
        cp_commit();                                                            \
    } while (0)

    // Prologue: fill STAGES-1 stages
#pragma unroll
    for (int s = 0; s < STAGES - 1; s++) LOAD_STAGE(s, s * BK);

    int sr = 0, sw = STAGES - 1;
    for (int k = 0; k < KITERS; k++) {
        cp_wait<STAGES - 2>();
        __syncthreads();

        // issue the next stage's loads (keeps pipeline full)
        if (k + STAGES - 1 < KITERS) LOAD_STAGE(sw, (k + STAGES - 1) * BK);
        else cp_commit();   // keep wait_group counting consistent

        const uint32_t sA = sbase + (uint32_t)sr * STAGE_BYTES;
        const uint32_t sB = sA + A_TILE_BYTES;

#pragma unroll
        for (int ks = 0; ks < BK / 16; ks++) {
            const uint32_t swz = (uint32_t)(((ks * 2 + colsel) ^ lane7)) * 16u;
            uint32_t a[4][4];
#pragma unroll
            for (int mt = 0; mt < 4; mt++)
                ldmatrix_x4(a[mt], sA + aRowOff[mt] + swz);
            uint32_t b[4][2];
            {
                uint32_t r[4];
                ldmatrix_x4(r, sB + bRow0 + swz);
                b[0][0] = r[0]; b[1][0] = r[1]; b[0][1] = r[2]; b[1][1] = r[3];
                ldmatrix_x4(r, sB + bRow1 + swz);
                b[2][0] = r[0]; b[3][0] = r[1]; b[2][1] = r[2]; b[3][1] = r[3];
            }
#pragma unroll
            for (int mt = 0; mt < 4; mt++)
#pragma unroll
                for (int nt = 0; nt < 4; nt++)
                    mma16816(acc[mt][nt], a[mt], b[nt]);
        }

        sr = (sr + 1) % STAGES;
        sw = (sw + 1) % STAGES;
    }

    // ------------------------------ epilogue -------------------------------
    const float sc = *scale_p;
    const int mbase = m0 + wm * 64 + (lane >> 2);
    const int nbase = n0 + wn * 32 + (lane & 3) * 2;
#pragma unroll
    for (int nt = 0; nt < 4; nt++) {
        const int n = nbase + nt * 8;
        const float2 bb = *reinterpret_cast<const float2*>(bias + n);
#pragma unroll
        for (int mt = 0; mt < 4; mt++) {
            const int m = mbase + mt * 16;
            float2 o0, o1;
            o0.x = acc[mt][nt][0] * sc + bb.x;
            o0.y = acc[mt][nt][1] * sc + bb.y;
            o1.x = acc[mt][nt][2] * sc + bb.x;
            o1.y = acc[mt][nt][3] * sc + bb.y;
            *reinterpret_cast<float2*>(out + (size_t)m * N_DIM + n) = o0;
            *reinterpret_cast<float2*>(out + (size_t)(m + 8) * N_DIM + n) = o1;
        }
    }
#undef LOAD_STAGE
}

// ---------------------------------------------------------------------------
// Host launch
// ---------------------------------------------------------------------------
extern "C" void kernel_launch(void* const* d_in, const int* in_sizes, int n_in,
                              void* d_out, int out_size) {
    (void)in_sizes; (void)n_in; (void)out_size;
    const float* x     = (const float*)d_in[0];
    const int*   w     = (const int*)d_in[1];
    const float* scale = (const float*)d_in[2];
    const float* bias  = (const float*)d_in[3];
    float*       out   = (float*)d_out;

    void *xh = nullptr, *wh = nullptr;
    cudaGetSymbolAddress(&xh, g_Xh);
    cudaGetSymbolAddress(&wh, g_Wh);

    {
        const int n8 = M_DIM * K_DIM / 8;
        fp4lin_cvt_x<<<n8 / 256, 256>>>((const float4*)x, (H8*)xh, n8);
        const int n4 = N_DIM * K_DIM / 4;
        fp4lin_cvt_w<<<n4 / 256, 256>>>((const int4*)w, (H4*)wh, n4);
    }

    static bool attr_set = false;
    if (!attr_set) {
        cudaFuncSetAttribute(fp4lin_gemm,
                             cudaFuncAttributeMaxDynamicSharedMemorySize,
                             SMEM_BYTES);
        attr_set = true;
    }
    dim3 grid(N_DIM / BN, M_DIM / BM);   // 32 x 64; x = n fastest
    fp4lin_gemm<<<grid, 256, SMEM_BYTES>>>((const __half*)xh, (const __half*)wh,
                                           scale, bias, out);
}

// round 10
// speedup vs baseline: 1.1887x; 1.0700x over previous
#include <cuda_runtime.h>
#include <cuda.h>
#include <cuda_fp16.h>
#include <cstdint>

// ---------------------------------------------------------------------------
// out[M,N] = x[M,K] @ (codes[N,K] * scale)^T + bias
// M=8192, N=4096, K=4096.  Baseline sm_100 ISA: HMMA m16n8k16 + ldmatrix.
// R8/R9: replace per-thread cp.async (8 LDGSTS x 8cyc structural floor per
// warp per k-iter + address math) with TMA bulk tensor loads issued by a
// single thread + mbarrier.  SMEM layout identical to the old XOR swizzle
// (= TMA SW128), so ldmatrix addressing is unchanged.  128x128x64 tile,
// 3 stages, 2 CTAs/SM, 8 warps (2m x 4n, 64x32 warp tile).
// (R9 bench was an infra failure; re-running the same experiment with a
//  tensormap prefetch added.)
// ---------------------------------------------------------------------------
#define M_DIM 8192
#define N_DIM 4096
#define K_DIM 4096

#define BM 128
#define BN 128
#define BK 64
#define STAGES 3
#define KITERS (K_DIM / BK)          // 64

#define A_TILE_BYTES (BM * BK * 2)   // 16 KB
#define B_TILE_BYTES (BN * BK * 2)   // 16 KB
#define STAGE_BYTES  (A_TILE_BYTES + B_TILE_BYTES)   // 32 KB
#define SMEM_TILES_OFF 1024
#define SMEM_BYTES (SMEM_TILES_OFF + STAGES * STAGE_BYTES)  // ~97 KB -> 2 CTAs/SM

// Scratch fp16 copies (device globals: allocation-free per harness rules)
__device__ __align__(1024) __half g_Xh[(size_t)M_DIM * K_DIM];   // 64 MB
__device__ __align__(1024) __half g_Wh[(size_t)N_DIM * K_DIM];   // 32 MB

// ---------------------------------------------------------------------------
// PTX helpers
// ---------------------------------------------------------------------------
__device__ __forceinline__ uint32_t smem_u32(const void* p) {
    uint32_t a;
    asm("{ .reg .u64 t; cvta.to.shared.u64 t, %1; cvt.u32.u64 %0, t; }"
        : "=r"(a) : "l"(p));
    return a;
}

#define MBARRIER_INIT(addr, count) \
    asm volatile("mbarrier.init.shared.b64 [%0], %1;" \
                 :: "r"((uint32_t)(addr)), "r"((uint32_t)(count)) : "memory")

#define MBARRIER_EXPECT_TX(addr, bytes) \
    asm volatile("mbarrier.arrive.expect_tx.shared.b64 _, [%0], %1;" \
                 :: "r"((uint32_t)(addr)), "r"((uint32_t)(bytes)) : "memory")

#define MBARRIER_WAIT_PARITY(addr, parity) do {                                   \
    uint32_t _mbar = (uint32_t)(addr);                                            \
    uint32_t _par  = (uint32_t)(parity);                                          \
    uint32_t _done;                                                               \
    asm volatile(                                                                 \
        "{\n\t.reg .pred p;\n\t"                                                  \
        "mbarrier.try_wait.parity.acquire.cta.shared::cta.b64 p, [%1], %2;\n\t"   \
        "selp.b32 %0, 1, 0, p;\n\t}"                                              \
        : "=r"(_done) : "r"(_mbar), "r"(_par) : "memory");                        \
    if (!_done) {                                                                 \
        asm volatile(                                                             \
            "{\n\t.reg .pred P1;\n\t"                                             \
            "WAIT_LOOP_%=:\n\t"                                                   \
            "mbarrier.try_wait.parity.acquire.cta.shared::cta.b64 P1, [%0], %1, 0x989680;\n\t" \
            "@P1 bra.uni WAIT_DONE_%=;\n\t"                                       \
            "bra.uni WAIT_LOOP_%=;\n\t"                                           \
            "WAIT_DONE_%=:\n\t}"                                                  \
            :: "r"(_mbar), "r"(_par) : "memory");                                 \
    }                                                                             \
} while (0)

#define FENCE_PROXY_ASYNC_SHARED_CTA() \
    asm volatile("fence.proxy.async.shared::cta;" ::: "memory")

__device__ __forceinline__ void tma_prefetch(const CUtensorMap* map) {
    asm volatile("prefetch.tensormap [%0];" :: "l"(map));
}

__device__ __forceinline__ void tma2d(uint32_t dst_smem, const CUtensorMap* map,
                                      int cx, int cy, uint32_t mbar) {
    asm volatile(
        "cp.async.bulk.tensor.2d.shared::cta.global.tile.mbarrier::complete_tx::bytes "
        "[%0], [%1, {%2, %3}], [%4];"
        :: "r"(dst_smem), "l"(map), "r"(cx), "r"(cy), "r"(mbar) : "memory");
}

__device__ __forceinline__ void ldmatrix_x4(uint32_t* r, uint32_t addr) {
    asm volatile("ldmatrix.sync.aligned.m8n8.x4.shared.b16 {%0,%1,%2,%3}, [%4];"
                 : "=r"(r[0]), "=r"(r[1]), "=r"(r[2]), "=r"(r[3]) : "r"(addr));
}

__device__ __forceinline__ void mma16816(float* c, const uint32_t* a,
                                         const uint32_t* b) {
    asm volatile(
        "mma.sync.aligned.m16n8k16.row.col.f32.f16.f16.f32 "
        "{%0,%1,%2,%3}, {%4,%5,%6,%7}, {%8,%9}, {%0,%1,%2,%3};"
        : "+f"(c[0]), "+f"(c[1]), "+f"(c[2]), "+f"(c[3])
        : "r"(a[0]), "r"(a[1]), "r"(a[2]), "r"(a[3]), "r"(b[0]), "r"(b[1]));
}

// ---------------------------------------------------------------------------
// Conversion pre-passes: fp32 x -> fp16, int32 codes -> fp16 (exact)
// ---------------------------------------------------------------------------
struct __align__(16) H8 { __half2 a, b, c, d; };
struct __align__(8)  H4 { __half2 a, b; };

__global__ void fp4lin_cvt_x(const float4* __restrict__ x, H8* __restrict__ o, int n8) {
    int i = blockIdx.x * blockDim.x + threadIdx.x;
    if (i >= n8) return;
    float4 v0 = x[2 * i], v1 = x[2 * i + 1];
    H8 h;
    h.a = __floats2half2_rn(v0.x, v0.y);
    h.b = __floats2half2_rn(v0.z, v0.w);
    h.c = __floats2half2_rn(v1.x, v1.y);
    h.d = __floats2half2_rn(v1.z, v1.w);
    o[i] = h;
}

__global__ void fp4lin_cvt_w(const int4* __restrict__ w, H4* __restrict__ o, int n4) {
    int i = blockIdx.x * blockDim.x + threadIdx.x;
    if (i >= n4) return;
    int4 v = w[i];
    H4 h;
    h.a = __halves2half2(__int2half_rn(v.x), __int2half_rn(v.y));
    h.b = __halves2half2(__int2half_rn(v.z), __int2half_rn(v.w));
    o[i] = h;
}

// ---------------------------------------------------------------------------
// GEMM: 128x128x64 CTA tile, 8 warps (2m x 4n, 64x32 warp tile),
// 3-stage TMA+mbarrier pipeline, SW128 SMEM, HMMA m16n8k16, 2 CTAs/SM.
// ---------------------------------------------------------------------------
__global__ void __launch_bounds__(256, 2)
fp4lin_gemm(const __grid_constant__ CUtensorMap tma_a,
            const __grid_constant__ CUtensorMap tma_b,
            const float* __restrict__ scale_p, const float* __restrict__ bias,
            float* __restrict__ out) {
    extern __shared__ __align__(1024) uint8_t smem[];
    const uint32_t sbase = smem_u32(smem);
    const int tid  = threadIdx.x;
    const int wid  = tid >> 5;
    const int lane = tid & 31;
    const int wm   = wid >> 2;          // 0..1  (m warp)
    const int wn   = wid & 3;           // 0..3  (n warp)
    const int m0   = blockIdx.y * BM;
    const int n0   = blockIdx.x * BN;

#define FULLB(s) (sbase + (uint32_t)(s) * 8u)
#define AOFF(s)  (sbase + SMEM_TILES_OFF + (uint32_t)(s) * STAGE_BYTES)
#define BOFF(s)  (AOFF(s) + A_TILE_BYTES)

    if (tid == 0) {
        tma_prefetch(&tma_a);
        tma_prefetch(&tma_b);
        for (int s = 0; s < STAGES; s++) MBARRIER_INIT(FULLB(s), 1);
        FENCE_PROXY_ASYNC_SHARED_CTA();
    }
    __syncthreads();

    // Prologue: fill STAGES-1 stages
    if (tid == 0) {
#pragma unroll
        for (int s = 0; s < STAGES - 1; s++) {
            MBARRIER_EXPECT_TX(FULLB(s), STAGE_BYTES);
            tma2d(AOFF(s), &tma_a, s * BK, m0, FULLB(s));
            tma2d(BOFF(s), &tma_b, s * BK, n0, FULLB(s));
        }
    }

    // --- ldmatrix per-lane components (SW128: byte ^ ((byte>>3)&0x70)) ---
    const int rowin  = (lane & 7) | (((lane >> 3) & 1) << 3);  // 0..15
    const int colsel = lane >> 4;                              // 0..1
    const int lane7  = lane & 7;
    uint32_t aRowOff[4];
#pragma unroll
    for (int t = 0; t < 4; t++)
        aRowOff[t] = (uint32_t)(wm * 64 + t * 16 + rowin) * 128u;
    const uint32_t bRow0 = (uint32_t)(wn * 32 + rowin) * 128u;
    const uint32_t bRow1 = (uint32_t)(wn * 32 + 16 + rowin) * 128u;

    float acc[4][4][4];
#pragma unroll
    for (int mt = 0; mt < 4; mt++)
#pragma unroll
        for (int nt = 0; nt < 4; nt++)
#pragma unroll
            for (int e = 0; e < 4; e++) acc[mt][nt][e] = 0.f;

    for (int k = 0; k < KITERS; k++) {
        const int sr = k % STAGES;
        const int ph = (k / STAGES) & 1;

        // All threads are past their reads of slot (k-1)%STAGES once they
        // reach this barrier -> safe for thread 0 to re-issue TMA into it.
        __syncthreads();
        const int kn = k + STAGES - 1;
        if (tid == 0 && kn < KITERS) {
            const int sw = kn % STAGES;
            MBARRIER_EXPECT_TX(FULLB(sw), STAGE_BYTES);
            tma2d(AOFF(sw), &tma_a, kn * BK, m0, FULLB(sw));
            tma2d(BOFF(sw), &tma_b, kn * BK, n0, FULLB(sw));
        }

        MBARRIER_WAIT_PARITY(FULLB(sr), ph);

        const uint32_t sA = AOFF(sr);
        const uint32_t sB = BOFF(sr);

#pragma unroll
        for (int ks = 0; ks < BK / 16; ks++) {
            const uint32_t swz = (uint32_t)(((ks * 2 + colsel) ^ lane7)) * 16u;
            uint32_t a[4][4];
#pragma unroll
            for (int mt = 0; mt < 4; mt++)
                ldmatrix_x4(a[mt], sA + aRowOff[mt] + swz);
            uint32_t b[4][2];
            {
                uint32_t r[4];
                ldmatrix_x4(r, sB + bRow0 + swz);
                b[0][0] = r[0]; b[1][0] = r[1]; b[0][1] = r[2]; b[1][1] = r[3];
                ldmatrix_x4(r, sB + bRow1 + swz);
                b[2][0] = r[0]; b[3][0] = r[1]; b[2][1] = r[2]; b[3][1] = r[3];
            }
#pragma unroll
            for (int mt = 0; mt < 4; mt++)
#pragma unroll
                for (int nt = 0; nt < 4; nt++)
                    mma16816(acc[mt][nt], a[mt], b[nt]);
        }
    }

    // ------------------------------ epilogue -------------------------------
    const float sc = *scale_p;
    const int mbase = m0 + wm * 64 + (lane >> 2);
    const int nbase = n0 + wn * 32 + (lane & 3) * 2;
#pragma unroll
    for (int nt = 0; nt < 4; nt++) {
        const int n = nbase + nt * 8;
        const float2 bb = *reinterpret_cast<const float2*>(bias + n);
#pragma unroll
        for (int mt = 0; mt < 4; mt++) {
            const int m = mbase + mt * 16;
            float2 o0, o1;
            o0.x = acc[mt][nt][0] * sc + bb.x;
            o0.y = acc[mt][nt][1] * sc + bb.y;
            o1.x = acc[mt][nt][2] * sc + bb.x;
            o1.y = acc[mt][nt][3] * sc + bb.y;
            *reinterpret_cast<float2*>(out + (size_t)m * N_DIM + n) = o0;
            *reinterpret_cast<float2*>(out + (size_t)(m + 8) * N_DIM + n) = o1;
        }
    }
#undef FULLB
#undef AOFF
#undef BOFF
}

// ---------------------------------------------------------------------------
// Host launch
// ---------------------------------------------------------------------------
typedef CUresult (*PFN_encTiled)(
    CUtensorMap*, CUtensorMapDataType, cuuint32_t, void*,
    const cuuint64_t*, const cuuint64_t*, const cuuint32_t*, const cuuint32_t*,
    CUtensorMapInterleave, CUtensorMapSwizzle, CUtensorMapL2promotion,
    CUtensorMapFloatOOBfill);

extern "C" void kernel_launch(void* const* d_in, const int* in_sizes, int n_in,
                              void* d_out, int out_size) {
    (void)in_sizes; (void)n_in; (void)out_size;
    const float* x     = (const float*)d_in[0];
    const int*   w     = (const int*)d_in[1];
    const float* scale = (const float*)d_in[2];
    const float* bias  = (const float*)d_in[3];
    float*       out   = (float*)d_out;

    void *xh = nullptr, *wh = nullptr;
    cudaGetSymbolAddress(&xh, g_Xh);
    cudaGetSymbolAddress(&wh, g_Wh);

    {
        const int n8 = M_DIM * K_DIM / 8;
        fp4lin_cvt_x<<<n8 / 256, 256>>>((const float4*)x, (H8*)xh, n8);
        const int n4 = N_DIM * K_DIM / 4;
        fp4lin_cvt_w<<<n4 / 256, 256>>>((const int4*)w, (H4*)wh, n4);
    }

    // Tensor maps (host-side; driver entry point, no -lcuda)
    CUtensorMap mapA, mapB;
    {
        PFN_encTiled enc = nullptr;
        cudaDriverEntryPointQueryResult qr;
        cudaGetDriverEntryPointByVersion("cuTensorMapEncodeTiled", (void**)&enc,
                                         12000, cudaEnableDefault, &qr);
        cuuint64_t dimsA[2] = {K_DIM, M_DIM};
        cuuint64_t strideA[1] = {K_DIM * 2};
        cuuint32_t box[2] = {BK, BM};
        cuuint32_t es[2] = {1, 1};
        enc(&mapA, CU_TENSOR_MAP_DATA_TYPE_FLOAT16, 2, xh, dimsA, strideA, box, es,
            CU_TENSOR_MAP_INTERLEAVE_NONE, CU_TENSOR_MAP_SWIZZLE_128B,
            CU_TENSOR_MAP_L2_PROMOTION_L2_128B, CU_TENSOR_MAP_FLOAT_OOB_FILL_NONE);
        cuuint64_t dimsB[2] = {K_DIM, N_DIM};
        cuuint32_t boxB[2] = {BK, BN};
        enc(&mapB, CU_TENSOR_MAP_DATA_TYPE_FLOAT16, 2, wh, dimsB, strideA, boxB, es,
            CU_TENSOR_MAP_INTERLEAVE_NONE, CU_TENSOR_MAP_SWIZZLE_128B,
            CU_TENSOR_MAP_L2_PROMOTION_L2_128B, CU_TENSOR_MAP_FLOAT_OOB_FILL_NONE);
    }

    static bool attr_set = false;
    if (!attr_set) {
        cudaFuncSetAttribute(fp4lin_gemm,
                             cudaFuncAttributeMaxDynamicSharedMemorySize,
                             SMEM_BYTES);
        attr_set = true;
    }
    dim3 grid(N_DIM / BN, M_DIM / BM);   // 32 x 64; x = n fastest
    fp4lin_gemm<<<grid, 256, SMEM_BYTES>>>(mapA, mapB, scale, bias, out);
}